// round 2
// baseline (speedup 1.0000x reference)
#include <cuda_runtime.h>
#include <cstdint>
#include <cstddef>

// ---------------------------------------------------------------------------
// MPConv fused GNN edge-MLP + scatter on GB300 (sm_103a)
//
//   A = x @ W1[0:64]   + b1      (precomputed per node)
//   B = x @ W1[64:128]           (precomputed per node)
//   per edge e: h = A[i] + B[j] + ea @ W1[128:160]
//               g = gelu_exact(layernorm(h) * gamma + beta)
//               m = g @ W2 + b2
//               out[j] += m      (vectorized atomic scatter)
// ---------------------------------------------------------------------------

#define NODES_MAX 100000
#define E_TILE    128
#define NTHREADS  256

// scratch: per-node precomputed A||B, 128 floats per node (51.2 MB)
__device__ __align__(16) float g_AB[(size_t)NODES_MAX * 128];
// edge_index dtype flag: 1 = int64 elements, 0 = int32 elements
__device__ int g_idx64;

__device__ __forceinline__ float gelu_exact(float v) {
    return 0.5f * v * (1.0f + erff(v * 0.70710678118654752440f));
}

#define FMA_ROW(ACC, A, B)                          \
    ACC.x = fmaf((A), (B).x, ACC.x);                \
    ACC.y = fmaf((A), (B).y, ACC.y);                \
    ACC.z = fmaf((A), (B).z, ACC.z);                \
    ACC.w = fmaf((A), (B).w, ACC.w);

// ---------------------------------------------------------------------------
__global__ void zero_kernel(float4* out, int n4) {
    int idx = blockIdx.x * blockDim.x + threadIdx.x;
    if (idx < n4) out[idx] = make_float4(0.f, 0.f, 0.f, 0.f);
}

// ---------------------------------------------------------------------------
// Detect whether edge_index buffer holds int64 or int32 elements.
// int32 data misread as int64 packs two random indices (a + b*2^32) and will
// exceed [0, N) with overwhelming probability over 128 samples.
__global__ void detect_idx_kernel(const void* edge_index, int N) {
    const long long* p64 = (const long long*)edge_index;
    int ok64 = 1;
    for (int e = 0; e < 128; ++e) {
        long long v = p64[e];
        if (v < 0 || v >= (long long)N) { ok64 = 0; break; }
    }
    g_idx64 = ok64;
}

__device__ __forceinline__ int load_edge_idx(const void* ei, long long pos, int idx64) {
    if (idx64) return (int)((const long long*)ei)[pos];
    return ((const int*)ei)[pos];
}

// ---------------------------------------------------------------------------
// Precompute g_AB[n][0:64] = x[n] @ W1[0:64] + b1 ; g_AB[n][64:128] = x[n] @ W1[64:128]
// block: 64 nodes x 128 channels, 256 threads, 8x4 microtile
// dyn smem: xT[64][64] (16KB) + Wcat[64][128] (32KB) = 48KB
__global__ void __launch_bounds__(NTHREADS, 2)
precompute_kernel(const float* __restrict__ x,
                  const float* __restrict__ W1,
                  const float* __restrict__ b1,
                  int N) {
    extern __shared__ float sm[];
    float* xT = sm;              // [k][node] : 64 x 64
    float* Wc = sm + 64 * 64;    // [k][c]    : 64 x 128

    int t = threadIdx.x;
    int n_base = blockIdx.x * 64;

#pragma unroll
    for (int it = 0; it < 32; ++it) {
        int idx = t + it * NTHREADS;          // 0..8191
        int k = idx >> 7, c = idx & 127;
        Wc[idx] = (c < 64) ? W1[k * 64 + c] : W1[(64 + k) * 64 + (c - 64)];
    }
#pragma unroll
    for (int it = 0; it < 16; ++it) {
        int idx = t + it * NTHREADS;          // 0..4095
        int node = idx >> 6, k = idx & 63;
        int gn = n_base + node;
        xT[k * 64 + node] = (gn < N) ? x[(size_t)gn * 64 + k] : 0.f;
    }
    __syncthreads();

    int tx = t & 31;           // channel group, c0 = tx*4  (0..124)
    int ty = t >> 5;           // node group,    n0 = ty*8
    int c0 = tx * 4, n0 = ty * 8;

    float4 acc[8];
#pragma unroll
    for (int r = 0; r < 8; ++r) acc[r] = make_float4(0.f, 0.f, 0.f, 0.f);

#pragma unroll 8
    for (int k = 0; k < 64; ++k) {
        float4 b  = *(const float4*)&Wc[k * 128 + c0];
        float4 a0 = *(const float4*)&xT[k * 64 + n0];
        float4 a1 = *(const float4*)&xT[k * 64 + n0 + 4];
        FMA_ROW(acc[0], a0.x, b); FMA_ROW(acc[1], a0.y, b);
        FMA_ROW(acc[2], a0.z, b); FMA_ROW(acc[3], a0.w, b);
        FMA_ROW(acc[4], a1.x, b); FMA_ROW(acc[5], a1.y, b);
        FMA_ROW(acc[6], a1.z, b); FMA_ROW(acc[7], a1.w, b);
    }

    float4 badd = make_float4(0.f, 0.f, 0.f, 0.f);
    if (c0 < 64) badd = *(const float4*)&b1[c0];

#pragma unroll
    for (int r = 0; r < 8; ++r) {
        int gn = n_base + n0 + r;
        if (gn < N) {
            float4 v = acc[r];
            v.x += badd.x; v.y += badd.y; v.z += badd.z; v.w += badd.w;
            *(float4*)&g_AB[(size_t)gn * 128 + c0] = v;
        }
    }
}

// ---------------------------------------------------------------------------
// Main edge kernel. block: 128 edges, 256 threads.
// dyn smem layout (bytes):
//   iidx[128] int      @ 0
//   jidx[128] int      @ 512
//   W1c [32][64]       @ 1024     (8 KB)
//   W2s [64][64]       @ 9216     (16 KB)
//   eaT [32][132]      @ 25600    (16.5 KB)
//   hT  [64][132]      @ 42496    (33 KB)
//   total 76288
__global__ void __launch_bounds__(NTHREADS, 2)
mpconv_kernel(const void* __restrict__ edge_index,
              const float* __restrict__ edge_attr,
              const float* __restrict__ W1,
              const float* __restrict__ gamma,
              const float* __restrict__ beta,
              const float* __restrict__ W2,
              const float* __restrict__ b2,
              float* __restrict__ out,
              int E) {
    extern __shared__ char smraw[];
    int*   iidx = (int*)smraw;
    int*   jidx = iidx + 128;
    float* W1c  = (float*)(smraw + 1024);
    float* W2s  = W1c + 32 * 64;
    float* eaT  = W2s + 64 * 64;
    float* hT   = eaT + 32 * 132;

    int t = threadIdx.x;
    long long e_base = (long long)blockIdx.x * E_TILE;
    int idx64 = g_idx64;

    // edge indices (E is a multiple of 128)
    if (t < 128) iidx[t] = load_edge_idx(edge_index, e_base + t, idx64);
    else         jidx[t - 128] = load_edge_idx(edge_index, (long long)E + e_base + (t - 128), idx64);

    // W1c = rows 128..159 of W1
#pragma unroll
    for (int it = 0; it < 8; ++it) {
        int idx = t + it * NTHREADS;          // 0..2047
        W1c[idx] = W1[128 * 64 + idx];
    }
#pragma unroll
    for (int it = 0; it < 16; ++it) {
        int idx = t + it * NTHREADS;          // 0..4095
        W2s[idx] = W2[idx];
    }
    // edge_attr transposed: eaT[k][e]
    {
        const float4* ea4 = (const float4*)edge_attr;
#pragma unroll
        for (int it = 0; it < 4; ++it) {
            int slot = t + it * NTHREADS;     // 0..1023
            int e = slot >> 3, q = slot & 7;
            float4 v = ea4[e_base * 8 + slot];
            int k = q * 4;
            eaT[(k + 0) * 132 + e] = v.x;
            eaT[(k + 1) * 132 + e] = v.y;
            eaT[(k + 2) * 132 + e] = v.z;
            eaT[(k + 3) * 132 + e] = v.w;
        }
    }
    __syncthreads();

    int tx = t & 15, ty = t >> 4;
    int c0 = tx * 4, e0 = ty * 8;

    // -------- GEMM1: h_edge = ea @ W1c --------
    float4 acc[8];
#pragma unroll
    for (int r = 0; r < 8; ++r) acc[r] = make_float4(0.f, 0.f, 0.f, 0.f);

#pragma unroll 8
    for (int k = 0; k < 32; ++k) {
        float4 b  = *(const float4*)&W1c[k * 64 + c0];
        float4 a0 = *(const float4*)&eaT[k * 132 + e0];
        float4 a1 = *(const float4*)&eaT[k * 132 + e0 + 4];
        FMA_ROW(acc[0], a0.x, b); FMA_ROW(acc[1], a0.y, b);
        FMA_ROW(acc[2], a0.z, b); FMA_ROW(acc[3], a0.w, b);
        FMA_ROW(acc[4], a1.x, b); FMA_ROW(acc[5], a1.y, b);
        FMA_ROW(acc[6], a1.z, b); FMA_ROW(acc[7], a1.w, b);
    }

    // -------- gather precomputed node parts: h += A[i] + B[j] --------
    const float4* AB4 = (const float4*)g_AB;
#pragma unroll
    for (int r = 0; r < 8; ++r) {
        int e = e0 + r;
        int vi = iidx[e], vj = jidx[e];
        float4 av = AB4[(size_t)vi * 32 + tx];        // A part, c0 = tx*4
        float4 bv = AB4[(size_t)vj * 32 + 16 + tx];   // B part
        acc[r].x += av.x + bv.x;
        acc[r].y += av.y + bv.y;
        acc[r].z += av.z + bv.z;
        acc[r].w += av.w + bv.w;
    }

    // -------- LayerNorm + GELU, write hT[k][e] --------
    float4 gmv = *(const float4*)&gamma[c0];
    float4 btv = *(const float4*)&beta[c0];
    float gbuf[4][8];

#pragma unroll
    for (int r = 0; r < 8; ++r) {
        float4 h = acc[r];
        float s  = h.x + h.y + h.z + h.w;
        float s2 = h.x * h.x + h.y * h.y + h.z * h.z + h.w * h.w;
        // reduce over the 16 tx-threads holding this edge's 64 channels
#pragma unroll
        for (int off = 8; off >= 1; off >>= 1) {
            s  += __shfl_xor_sync(0xffffffffu, s,  off, 16);
            s2 += __shfl_xor_sync(0xffffffffu, s2, off, 16);
        }
        float mu   = s * (1.0f / 64.0f);
        float var  = s2 * (1.0f / 64.0f) - mu * mu;
        float rstd = rsqrtf(var + 1e-5f);
        gbuf[0][r] = gelu_exact((h.x - mu) * rstd * gmv.x + btv.x);
        gbuf[1][r] = gelu_exact((h.y - mu) * rstd * gmv.y + btv.y);
        gbuf[2][r] = gelu_exact((h.z - mu) * rstd * gmv.z + btv.z);
        gbuf[3][r] = gelu_exact((h.w - mu) * rstd * gmv.w + btv.w);
    }
#pragma unroll
    for (int cc = 0; cc < 4; ++cc) {
        float4 lo = make_float4(gbuf[cc][0], gbuf[cc][1], gbuf[cc][2], gbuf[cc][3]);
        float4 hi = make_float4(gbuf[cc][4], gbuf[cc][5], gbuf[cc][6], gbuf[cc][7]);
        *(float4*)&hT[(c0 + cc) * 132 + e0]     = lo;
        *(float4*)&hT[(c0 + cc) * 132 + e0 + 4] = hi;
    }
    __syncthreads();

    // -------- GEMM2: m = g @ W2 --------
    float4 acc2[8];
#pragma unroll
    for (int r = 0; r < 8; ++r) acc2[r] = make_float4(0.f, 0.f, 0.f, 0.f);

#pragma unroll 8
    for (int k = 0; k < 64; ++k) {
        float4 b  = *(const float4*)&W2s[k * 64 + c0];
        float4 a0 = *(const float4*)&hT[k * 132 + e0];
        float4 a1 = *(const float4*)&hT[k * 132 + e0 + 4];
        FMA_ROW(acc2[0], a0.x, b); FMA_ROW(acc2[1], a0.y, b);
        FMA_ROW(acc2[2], a0.z, b); FMA_ROW(acc2[3], a0.w, b);
        FMA_ROW(acc2[4], a1.x, b); FMA_ROW(acc2[5], a1.y, b);
        FMA_ROW(acc2[6], a1.z, b); FMA_ROW(acc2[7], a1.w, b);
    }

    // -------- scatter-add onto out[j] --------
    float4 b2v = *(const float4*)&b2[c0];
#pragma unroll
    for (int r = 0; r < 8; ++r) {
        int e = e0 + r;
        int vj = jidx[e];
        float4 v = acc2[r];
        v.x += b2v.x; v.y += b2v.y; v.z += b2v.z; v.w += b2v.w;
        float* p = out + (size_t)vj * 64 + c0;
        asm volatile("red.global.add.v4.f32 [%0], {%1,%2,%3,%4};"
                     :: "l"(p), "f"(v.x), "f"(v.y), "f"(v.z), "f"(v.w)
                     : "memory");
    }
}

// ---------------------------------------------------------------------------
extern "C" void kernel_launch(void* const* d_in, const int* in_sizes, int n_in,
                              void* d_out, int out_size) {
    const float* x          = (const float*)d_in[0];
    const void*  edge_index = d_in[1];
    const float* edge_attr  = (const float*)d_in[2];
    const float* W1         = (const float*)d_in[3];
    const float* b1         = (const float*)d_in[4];
    const float* gamma      = (const float*)d_in[5];
    const float* beta       = (const float*)d_in[6];
    const float* W2         = (const float*)d_in[7];
    const float* b2         = (const float*)d_in[8];
    float*       out        = (float*)d_out;

    int N = in_sizes[0] / 64;     // 100000
    int E = in_sizes[2] / 32;     // 1600000

    const int SM_PRE  = (64 * 64 + 64 * 128) * 4;                                    // 49152
    const int SM_MAIN = 1024 + (32 * 64 + 64 * 64 + 32 * 132 + 64 * 132) * 4;        // 76288
    cudaFuncSetAttribute(precompute_kernel, cudaFuncAttributeMaxDynamicSharedMemorySize, SM_PRE);
    cudaFuncSetAttribute(mpconv_kernel,     cudaFuncAttributeMaxDynamicSharedMemorySize, SM_MAIN);

    int n4 = out_size / 4;
    detect_idx_kernel<<<1, 1>>>(edge_index, N);
    zero_kernel<<<(n4 + 255) / 256, 256>>>((float4*)out, n4);
    precompute_kernel<<<(N + 63) / 64, NTHREADS, SM_PRE>>>(x, W1, b1, N);
    mpconv_kernel<<<E / E_TILE, NTHREADS, SM_MAIN>>>(edge_index, edge_attr, W1,
                                                     gamma, beta, W2, b2, out, E);
}